// round 14
// baseline (speedup 1.0000x reference)
#include <cuda_runtime.h>
#include <math.h>

#define BSZ 1024
#define ISZ 2048
#define OSZ 1024
#define NW  32        // B/32 batch bit-words
#define SEQ 32
#define CSTRIDE 256   // CSR slots per batch (mean nnz ~102, +15 sigma < 256)

// ---------------- device state (all re-initialized every launch) -------------
__device__ float    g_wT[(ISZ+1)*OSZ]; // weight [I][O] (+ zero row at i=ISZ)
__device__ float    g_A [ISZ*OSZ];     // running A = sum d^{t-k} M_k, [I][O]
__device__ unsigned g_sb[NW*ISZ];      // input spike bits, [bg][i]
__device__ unsigned g_zb[NW*OSZ];      // output spike bits, [bg][o]
__device__ float    g_S [ISZ];         // per-input batch spike counts
__device__ float    g_vf[BSZ*OSZ];     // fallback v if out_size too small
__device__ unsigned short g_csr[BSZ*CSTRIDE];  // per-batch spiking-i lists
__device__ unsigned g_ns[BSZ];         // padded (x8) list length per batch

// ---------------- K0a: build input bitmasks + column counts ------------------
__global__ void k_build_s(const float* __restrict__ s) {
    int id = blockIdx.x * blockDim.x + threadIdx.x;
    if (id >= NW * ISZ) return;
    int i  = id & (ISZ - 1);
    int bg = id >> 11;
    unsigned w = 0u;
#pragma unroll
    for (int k = 0; k < 32; k++) {
        float x = s[(bg * 32 + k) * ISZ + i];
        w |= (x != 0.0f ? 1u : 0u) << k;
    }
    g_sb[bg * ISZ + i] = w;
    atomicAdd(&g_S[i], (float)__popc(w));   // exact integer adds: order-independent
}

// ---------------- K0c: build per-batch CSR spike lists (ballot scan) ---------
// One warp per batch; ascending i order; padded to a multiple of 8 with i=ISZ
// (a zero weight row), so the gather loop is branch-free.
__global__ __launch_bounds__(256) void k_build_csr(const float* __restrict__ s) {
    int b    = (blockIdx.x * 256 + threadIdx.x) >> 5;   // batch 0..1023
    int lane = threadIdx.x & 31;
    const float* row = s + (size_t)b * ISZ;
    unsigned short* out = g_csr + b * CSTRIDE;
    unsigned base = 0;
    for (int c = 0; c < ISZ / 32; c++) {
        float x = row[c * 32 + lane];
        unsigned m = __ballot_sync(0xFFFFFFFFu, x != 0.0f);
        if (m & (1u << lane)) {
            int pos = base + __popc(m & ((1u << lane) - 1u));
            out[pos] = (unsigned short)(c * 32 + lane);
        }
        base += __popc(m);
    }
    unsigned padded = (base + 7u) & ~7u;
    for (unsigned j = base + lane; j < padded; j += 32)
        out[j] = (unsigned short)ISZ;                   // zero-row pad
    if (lane == 0) g_ns[b] = padded;
}

// ---------------- K0b: tiled transpose weight [O][I] -> wT [I][O] ------------
__global__ __launch_bounds__(256) void k_wT(const float* __restrict__ w) {
    __shared__ float tile[32][33];
    int tx = threadIdx.x, ty = threadIdx.y;           // block (32, 8)
    int x = blockIdx.x * 32 + tx;                     // i
    int y = blockIdx.y * 32 + ty;                     // o
#pragma unroll
    for (int j = 0; j < 32; j += 8)
        tile[ty + j][tx] = w[(size_t)(y + j) * ISZ + x];
    __syncthreads();
    int xo = blockIdx.y * 32 + tx;
    int yi = blockIdx.x * 32 + ty;
#pragma unroll
    for (int j = 0; j < 32; j += 8)
        g_wT[(size_t)(yi + j) * OSZ + xo] = tile[tx][ty + j];
}

// ---------------- K1: CSR-gather forward + LIF + spike-bit build -------------
// grid (O/64, B/32), block (32, 32). Warp = one batch; lane owns outputs
// (o, o+32): the second weight load is the same address +128 bytes (imm
// offset), so the index decode + IMAD.WIDE are amortized over 2 outputs.
// Register accumulation, fixed order per output -> deterministic.
__global__ __launch_bounds__(1024) void k_fwd(const float* __restrict__ bias,
                                              float* __restrict__ v,
                                              float* __restrict__ zout,
                                              float vdecay, int last) {
    __shared__ unsigned short sidx[32 * CSTRIDE];     // 16KB
    __shared__ unsigned char  spk[32][64];            // 2KB pred matrix [b][o]
    int lane = threadIdx.x;
    int wy   = threadIdx.y;                           // batch-in-group
    int b    = blockIdx.y * 32 + wy;
    int o    = blockIdx.x * 64 + lane;                // and o+32

    unsigned n = g_ns[b];
    {
        const unsigned short* src = g_csr + b * CSTRIDE;
        for (int k = lane; k < CSTRIDE; k += 32) sidx[wy * CSTRIDE + k] = src[k];
    }
    __syncwarp();                                     // per-warp private list

    const float* wrow = g_wT + o;
    float a0 = 0.0f, a1 = 0.0f, a2 = 0.0f, a3 = 0.0f;   // o partials
    float c0 = 0.0f, c1 = 0.0f, c2 = 0.0f, c3 = 0.0f;   // o+32 partials
    const uint4* q4 = (const uint4*)(sidx + wy * CSTRIDE);
    unsigned n8 = n >> 3;
    for (unsigned k = 0; k < n8; k++) {
        uint4 q = q4[k];                              // 8 packed u16 indices
        const float* p0 = wrow + (q.x & 0xFFFFu) * OSZ;
        const float* p1 = wrow + (q.x >> 16)     * OSZ;
        const float* p2 = wrow + (q.y & 0xFFFFu) * OSZ;
        const float* p3 = wrow + (q.y >> 16)     * OSZ;
        const float* p4 = wrow + (q.z & 0xFFFFu) * OSZ;
        const float* p5 = wrow + (q.z >> 16)     * OSZ;
        const float* p6 = wrow + (q.w & 0xFFFFu) * OSZ;
        const float* p7 = wrow + (q.w >> 16)     * OSZ;
        a0 += p0[0];  c0 += p0[32];
        a1 += p1[0];  c1 += p1[32];
        a2 += p2[0];  c2 += p2[32];
        a3 += p3[0];  c3 += p3[32];
        a0 += p4[0];  c0 += p4[32];
        a1 += p5[0];  c1 += p5[32];
        a2 += p6[0];  c2 += p6[32];
        a3 += p7[0];  c3 += p7[32];
    }
    float sumA = (a0 + a1) + (a2 + a3);               // fixed, deterministic
    float sumC = (c0 + c1) + (c2 + c3);

    {
        int idxv = b * OSZ + o;
        float vv = v[idxv] * vdecay + sumA + __ldg(&bias[o]);
        bool sp = (vv >= 1.0f);
        if (last) zout[idxv] = sp ? 1.0f : 0.0f;
        v[idxv] = sp ? 0.0f : vv;                     // v*(1-z) exactly
        spk[wy][lane] = (unsigned char)sp;
    }
    {
        int idxv = b * OSZ + o + 32;
        float vv = v[idxv] * vdecay + sumC + __ldg(&bias[o + 32]);
        bool sp = (vv >= 1.0f);
        if (last) zout[idxv] = sp ? 1.0f : 0.0f;
        v[idxv] = sp ? 0.0f : vv;
        spk[wy][lane + 32] = (unsigned char)sp;
    }
    __syncthreads();

    if (wy < 2) {                                     // bit-transpose 32x64
        int oc = wy * 32 + lane;
        unsigned wd = 0u;
#pragma unroll
        for (int k = 0; k < 32; k++)
            wd |= ((unsigned)spk[k][oc]) << k;
        g_zb[blockIdx.y * OSZ + blockIdx.x * 64 + oc] = wd;
    }
}

// ---------------- K2: M = z^T s popcount + A + w update, 4x4 register tile ---
// grid (O/64, I/32), block 128. Thread owns a 4o x 4il cell block.
__global__ __launch_bounds__(128) void k_upd(float a_t, float b_t, float c_t,
                                             float dpost, float etap, float etam) {
    __shared__ unsigned zt[NW * 64];   // [w][o-lane]   8KB
    __shared__ unsigned st[NW * 32];   // [w][il]       4KB
    __shared__ float    Ssh[32];
    int tid = threadIdx.x;
    int o0  = blockIdx.x * 64;
    int i0  = blockIdx.y * 32;

    for (int j = tid; j < NW * 64; j += 128) {
        int w = j >> 6, oo = j & 63;
        zt[j] = g_zb[w * OSZ + o0 + oo];
    }
    for (int j = tid; j < NW * 32; j += 128) {
        int w = j >> 5, il = j & 31;
        st[j] = g_sb[w * ISZ + i0 + il];
    }
    if (tid < 32) Ssh[tid] = g_S[i0 + tid];
    __syncthreads();

    int oq = (tid & 15) << 2;          // o-quad 0..60
    int iq = (tid >> 4) << 2;          // il-quad 0..28

    int cnt[16];
#pragma unroll
    for (int k = 0; k < 16; k++) cnt[k] = 0;
    int zc0 = 0, zc1 = 0, zc2 = 0, zc3 = 0;

#pragma unroll 8
    for (int w = 0; w < NW; w++) {
        uint4 z4 = *(const uint4*)&zt[w * 64 + oq];
        uint4 s4 = *(const uint4*)&st[w * 32 + iq];
        zc0 += __popc(z4.x); zc1 += __popc(z4.y);
        zc2 += __popc(z4.z); zc3 += __popc(z4.w);
        cnt[ 0] += __popc(s4.x & z4.x); cnt[ 1] += __popc(s4.x & z4.y);
        cnt[ 2] += __popc(s4.x & z4.z); cnt[ 3] += __popc(s4.x & z4.w);
        cnt[ 4] += __popc(s4.y & z4.x); cnt[ 5] += __popc(s4.y & z4.y);
        cnt[ 6] += __popc(s4.y & z4.z); cnt[ 7] += __popc(s4.y & z4.w);
        cnt[ 8] += __popc(s4.z & z4.x); cnt[ 9] += __popc(s4.z & z4.y);
        cnt[10] += __popc(s4.z & z4.z); cnt[11] += __popc(s4.z & z4.w);
        cnt[12] += __popc(s4.w & z4.x); cnt[13] += __popc(s4.w & z4.y);
        cnt[14] += __popc(s4.w & z4.z); cnt[15] += __popc(s4.w & z4.w);
    }
    float Zf0 = (float)zc0, Zf1 = (float)zc1, Zf2 = (float)zc2, Zf3 = (float)zc3;

#pragma unroll
    for (int c = 0; c < 4; c++) {
        int il  = iq + c;
        int idx = (i0 + il) * OSZ + o0 + oq;
        float Sv = Ssh[il];
        float4 Av = *(const float4*)&g_A[idx];
        float m0 = (float)cnt[c * 4 + 0], m1 = (float)cnt[c * 4 + 1];
        float m2 = (float)cnt[c * 4 + 2], m3 = (float)cnt[c * 4 + 3];
        float4 An;
        An.x = Av.x * dpost + m0;  An.y = Av.y * dpost + m1;
        An.z = Av.z * dpost + m2;  An.w = Av.w * dpost + m3;
        *(float4*)&g_A[idx] = An;
        float4 Wv = *(const float4*)&g_wT[idx];
        float cs = c_t * Sv;
        Wv.x += etap * (a_t * Zf0 + b_t * m0) - etam * (cs + An.x);
        Wv.y += etap * (a_t * Zf1 + b_t * m1) - etam * (cs + An.y);
        Wv.z += etap * (a_t * Zf2 + b_t * m2) - etam * (cs + An.z);
        Wv.w += etap * (a_t * Zf3 + b_t * m3) - etam * (cs + An.w);
        Wv.x = fminf(fmaxf(Wv.x, -1.0f), 1.0f);
        Wv.y = fminf(fmaxf(Wv.y, -1.0f), 1.0f);
        Wv.z = fminf(fmaxf(Wv.z, -1.0f), 1.0f);
        Wv.w = fminf(fmaxf(Wv.w, -1.0f), 1.0f);
        *(float4*)&g_wT[idx] = Wv;
    }
}

// ---------------- K3: tiled transpose wT [I][O] -> output [O][I] -------------
__global__ __launch_bounds__(256) void k_wout(float* __restrict__ out) {
    __shared__ float tile[32][33];
    int tx = threadIdx.x, ty = threadIdx.y;           // block (32, 8)
    int x = blockIdx.x * 32 + tx;                     // o
    int y = blockIdx.y * 32 + ty;                     // i
#pragma unroll
    for (int j = 0; j < 32; j += 8)
        tile[ty + j][tx] = g_wT[(size_t)(y + j) * OSZ + x];
    __syncthreads();
    int xi = blockIdx.y * 32 + tx;
    int yo = blockIdx.x * 32 + ty;
#pragma unroll
    for (int j = 0; j < 32; j += 8)
        out[(size_t)(yo + j) * ISZ + xi] = tile[tx][ty + j];
}

// -----------------------------------------------------------------------------
extern "C" void kernel_launch(void* const* d_in, const int* in_sizes, int n_in,
                              void* d_out, int out_size) {
    const float* s    = (const float*)d_in[0];   // input_spikes [B,I]
    const float* w    = (const float*)d_in[1];   // weight [O,I]
    const float* bias = (const float*)d_in[2];   // bias [O]
    float* out  = (float*)d_out;
    float* zout = out;

    void *pA = nullptr, *pS = nullptr, *pV = nullptr, *pW = nullptr;
    cudaGetSymbolAddress(&pA, g_A);
    cudaGetSymbolAddress(&pS, g_S);
    cudaGetSymbolAddress(&pV, g_vf);
    cudaGetSymbolAddress(&pW, g_wT);

    float* v = (out_size >= 2 * BSZ * OSZ) ? (out + BSZ * OSZ) : (float*)pV;

    // per-launch state init (graph-replayed every run -> deterministic)
    cudaMemsetAsync(pA, 0, (size_t)ISZ * OSZ * sizeof(float));
    cudaMemsetAsync(pS, 0, (size_t)ISZ * sizeof(float));
    cudaMemsetAsync(v,  0, (size_t)BSZ * OSZ * sizeof(float));
    cudaMemsetAsync((char*)pW + (size_t)ISZ * OSZ * sizeof(float), 0,
                    OSZ * sizeof(float));        // zero pad row i=ISZ

    k_build_s<<<(NW * ISZ) / 256, 256>>>(s);
    k_build_csr<<<BSZ / 8, 256>>>(s);
    k_wT<<<dim3(ISZ / 32, OSZ / 32), dim3(32, 8)>>>(w);

    // fp32-iterated trace constants, matching the reference's iterative decay
    const float d = (float)exp(-0.05);   // decay_pre = decay_post = v_decay
    float p0 = 1.0f, p1 = 1.0f;
    for (int t = 0; t < SEQ; t++) {
        p0 = p0 * d;                 // tpre/tpost trajectory for s=0 (= d^t, fp32)
        p1 = p1 * d + 1.0f;          // tpre trajectory for s=1
        k_fwd<<<dim3(OSZ / 64, BSZ / 32), dim3(32, 32)>>>(bias, v, zout, d, t == SEQ - 1);
        k_upd<<<dim3(OSZ / 64, ISZ / 32), 128>>>(p0, p1 - p0, p0, d, 1e-3f, 1e-3f);
    }

    if (out_size >= 2 * BSZ * OSZ + ISZ * OSZ)
        k_wout<<<dim3(OSZ / 32, ISZ / 32), dim3(32, 8)>>>(out + 2 * BSZ * OSZ);
}

// round 15
// speedup vs baseline: 1.0763x; 1.0763x over previous
#include <cuda_runtime.h>
#include <math.h>

#define BSZ 1024
#define ISZ 2048
#define OSZ 1024
#define NW  32        // B/32 batch bit-words
#define SEQ 32
#define CSTRIDE 256   // CSR slots per batch (mean nnz ~102, +15 sigma < 256)

// ---------------- device state (all re-initialized every launch) -------------
__device__ float    g_wT[(ISZ+1)*OSZ]; // weight [I][O] (+ zero row at i=ISZ)
__device__ float    g_A [ISZ*OSZ];     // running A = sum d^{t-k} M_k, [I][O]
__device__ unsigned g_sb[NW*ISZ];      // input spike bits, [bg][i]
__device__ unsigned g_zb[NW*OSZ];      // output spike bits, [bg][o]
__device__ float    g_S [ISZ];         // per-input batch spike counts
__device__ float    g_vf[BSZ*OSZ];     // fallback v if out_size too small
__device__ unsigned short g_csr[BSZ*CSTRIDE];  // per-batch spiking-i lists
__device__ unsigned g_ns[BSZ];         // padded (x8) list length per batch

// ---------------- K0a: build input bitmasks + column counts ------------------
__global__ void k_build_s(const float* __restrict__ s) {
    int id = blockIdx.x * blockDim.x + threadIdx.x;
    if (id >= NW * ISZ) return;
    int i  = id & (ISZ - 1);
    int bg = id >> 11;
    unsigned w = 0u;
#pragma unroll
    for (int k = 0; k < 32; k++) {
        float x = s[(bg * 32 + k) * ISZ + i];
        w |= (x != 0.0f ? 1u : 0u) << k;
    }
    g_sb[bg * ISZ + i] = w;
    atomicAdd(&g_S[i], (float)__popc(w));   // exact integer adds: order-independent
}

// ---------------- K0c: build per-batch CSR spike lists (ballot scan) ---------
// One warp per batch; ascending i order; padded to a multiple of 8 with i=ISZ
// (a zero weight row), so the gather loop is branch-free.
__global__ __launch_bounds__(256) void k_build_csr(const float* __restrict__ s) {
    int b    = (blockIdx.x * 256 + threadIdx.x) >> 5;   // batch 0..1023
    int lane = threadIdx.x & 31;
    const float* row = s + (size_t)b * ISZ;
    unsigned short* out = g_csr + b * CSTRIDE;
    unsigned base = 0;
    for (int c = 0; c < ISZ / 32; c++) {
        float x = row[c * 32 + lane];
        unsigned m = __ballot_sync(0xFFFFFFFFu, x != 0.0f);
        if (m & (1u << lane)) {
            int pos = base + __popc(m & ((1u << lane) - 1u));
            out[pos] = (unsigned short)(c * 32 + lane);
        }
        base += __popc(m);
    }
    unsigned padded = (base + 7u) & ~7u;
    for (unsigned j = base + lane; j < padded; j += 32)
        out[j] = (unsigned short)ISZ;                   // zero-row pad
    if (lane == 0) g_ns[b] = padded;
}

// ---------------- K0b: tiled transpose weight [O][I] -> wT [I][O] ------------
__global__ __launch_bounds__(256) void k_wT(const float* __restrict__ w) {
    __shared__ float tile[32][33];
    int tx = threadIdx.x, ty = threadIdx.y;           // block (32, 8)
    int x = blockIdx.x * 32 + tx;                     // i
    int y = blockIdx.y * 32 + ty;                     // o
#pragma unroll
    for (int j = 0; j < 32; j += 8)
        tile[ty + j][tx] = w[(size_t)(y + j) * ISZ + x];
    __syncthreads();
    int xo = blockIdx.y * 32 + tx;
    int yi = blockIdx.x * 32 + ty;
#pragma unroll
    for (int j = 0; j < 32; j += 8)
        g_wT[(size_t)(yi + j) * OSZ + xo] = tile[tx][ty + j];
}

// ---------------- K1: CSR-gather forward + LIF + spike-bit build -------------
// grid (O/64, B/16), block (32, 16) = 512 threads. Warp = one batch; lane owns
// outputs (o, o+32) so the index decode + IMAD.WIDE amortize over 2 outputs.
// 512-thread CTAs keep 3 CTAs/SM resident (48 warps, ~75% occ) unlike the
// 1024-thread variant (reg-file limited to 1 CTA). Spike bits are written as
// disjoint u16 halves of g_zb (no atomics; little-endian low half = batches
// 0-15 of the 32-batch word). Register accumulation, fixed order per output.
__global__ __launch_bounds__(512) void k_fwd(const float* __restrict__ bias,
                                             float* __restrict__ v,
                                             float* __restrict__ zout,
                                             float vdecay, int last) {
    __shared__ unsigned short sidx[16 * CSTRIDE];     // 8KB
    __shared__ unsigned char  spk[16][64];            // 1KB pred matrix [b][o]
    int lane = threadIdx.x;
    int wy   = threadIdx.y;                           // batch-in-group 0..15
    int b    = blockIdx.y * 16 + wy;
    int o    = blockIdx.x * 64 + lane;                // and o+32

    unsigned n = g_ns[b];
    {
        const unsigned short* src = g_csr + b * CSTRIDE;
        for (int k = lane; k < CSTRIDE; k += 32) sidx[wy * CSTRIDE + k] = src[k];
    }
    __syncwarp();                                     // per-warp private list

    const float* wrow = g_wT + o;
    float a0 = 0.0f, a1 = 0.0f, a2 = 0.0f, a3 = 0.0f;   // o partials
    float c0 = 0.0f, c1 = 0.0f, c2 = 0.0f, c3 = 0.0f;   // o+32 partials
    const uint4* q4 = (const uint4*)(sidx + wy * CSTRIDE);
    unsigned n8 = n >> 3;
    for (unsigned k = 0; k < n8; k++) {
        uint4 q = q4[k];                              // 8 packed u16 indices
        const float* p0 = wrow + (q.x & 0xFFFFu) * OSZ;
        const float* p1 = wrow + (q.x >> 16)     * OSZ;
        const float* p2 = wrow + (q.y & 0xFFFFu) * OSZ;
        const float* p3 = wrow + (q.y >> 16)     * OSZ;
        const float* p4 = wrow + (q.z & 0xFFFFu) * OSZ;
        const float* p5 = wrow + (q.z >> 16)     * OSZ;
        const float* p6 = wrow + (q.w & 0xFFFFu) * OSZ;
        const float* p7 = wrow + (q.w >> 16)     * OSZ;
        a0 += p0[0];  c0 += p0[32];
        a1 += p1[0];  c1 += p1[32];
        a2 += p2[0];  c2 += p2[32];
        a3 += p3[0];  c3 += p3[32];
        a0 += p4[0];  c0 += p4[32];
        a1 += p5[0];  c1 += p5[32];
        a2 += p6[0];  c2 += p6[32];
        a3 += p7[0];  c3 += p7[32];
    }
    float sumA = (a0 + a1) + (a2 + a3);               // fixed, deterministic
    float sumC = (c0 + c1) + (c2 + c3);

    {
        int idxv = b * OSZ + o;
        float vv = v[idxv] * vdecay + sumA + __ldg(&bias[o]);
        bool sp = (vv >= 1.0f);
        if (last) zout[idxv] = sp ? 1.0f : 0.0f;
        v[idxv] = sp ? 0.0f : vv;                     // v*(1-z) exactly
        spk[wy][lane] = (unsigned char)sp;
    }
    {
        int idxv = b * OSZ + o + 32;
        float vv = v[idxv] * vdecay + sumC + __ldg(&bias[o + 32]);
        bool sp = (vv >= 1.0f);
        if (last) zout[idxv] = sp ? 1.0f : 0.0f;
        v[idxv] = sp ? 0.0f : vv;
        spk[wy][lane + 32] = (unsigned char)sp;
    }
    __syncthreads();

    if (wy < 2) {                                     // bit-transpose 16x64
        int oc = wy * 32 + lane;
        unsigned short wd = 0;
#pragma unroll
        for (int k = 0; k < 16; k++)
            wd |= (unsigned short)(spk[k][oc] << k);
        int bg   = blockIdx.y >> 1;                   // 32-batch word index
        int half = blockIdx.y & 1;                    // low/high 16 bits
        unsigned short* dst =
            (unsigned short*)&g_zb[bg * OSZ + blockIdx.x * 64 + oc];
        dst[half] = wd;                               // disjoint u16, race-free
    }
}

// ---------------- K2: M = z^T s popcount + A + w update, 4x4 register tile ---
// grid (O/64, I/32), block 128. Thread owns a 4o x 4il cell block.
__global__ __launch_bounds__(128) void k_upd(float a_t, float b_t, float c_t,
                                             float dpost, float etap, float etam) {
    __shared__ unsigned zt[NW * 64];   // [w][o-lane]   8KB
    __shared__ unsigned st[NW * 32];   // [w][il]       4KB
    __shared__ float    Ssh[32];
    int tid = threadIdx.x;
    int o0  = blockIdx.x * 64;
    int i0  = blockIdx.y * 32;

    for (int j = tid; j < NW * 64; j += 128) {
        int w = j >> 6, oo = j & 63;
        zt[j] = g_zb[w * OSZ + o0 + oo];
    }
    for (int j = tid; j < NW * 32; j += 128) {
        int w = j >> 5, il = j & 31;
        st[j] = g_sb[w * ISZ + i0 + il];
    }
    if (tid < 32) Ssh[tid] = g_S[i0 + tid];
    __syncthreads();

    int oq = (tid & 15) << 2;          // o-quad 0..60
    int iq = (tid >> 4) << 2;          // il-quad 0..28

    int cnt[16];
#pragma unroll
    for (int k = 0; k < 16; k++) cnt[k] = 0;
    int zc0 = 0, zc1 = 0, zc2 = 0, zc3 = 0;

#pragma unroll 8
    for (int w = 0; w < NW; w++) {
        uint4 z4 = *(const uint4*)&zt[w * 64 + oq];
        uint4 s4 = *(const uint4*)&st[w * 32 + iq];
        zc0 += __popc(z4.x); zc1 += __popc(z4.y);
        zc2 += __popc(z4.z); zc3 += __popc(z4.w);
        cnt[ 0] += __popc(s4.x & z4.x); cnt[ 1] += __popc(s4.x & z4.y);
        cnt[ 2] += __popc(s4.x & z4.z); cnt[ 3] += __popc(s4.x & z4.w);
        cnt[ 4] += __popc(s4.y & z4.x); cnt[ 5] += __popc(s4.y & z4.y);
        cnt[ 6] += __popc(s4.y & z4.z); cnt[ 7] += __popc(s4.y & z4.w);
        cnt[ 8] += __popc(s4.z & z4.x); cnt[ 9] += __popc(s4.z & z4.y);
        cnt[10] += __popc(s4.z & z4.z); cnt[11] += __popc(s4.z & z4.w);
        cnt[12] += __popc(s4.w & z4.x); cnt[13] += __popc(s4.w & z4.y);
        cnt[14] += __popc(s4.w & z4.z); cnt[15] += __popc(s4.w & z4.w);
    }
    float Zf0 = (float)zc0, Zf1 = (float)zc1, Zf2 = (float)zc2, Zf3 = (float)zc3;

#pragma unroll
    for (int c = 0; c < 4; c++) {
        int il  = iq + c;
        int idx = (i0 + il) * OSZ + o0 + oq;
        float Sv = Ssh[il];
        float4 Av = *(const float4*)&g_A[idx];
        float m0 = (float)cnt[c * 4 + 0], m1 = (float)cnt[c * 4 + 1];
        float m2 = (float)cnt[c * 4 + 2], m3 = (float)cnt[c * 4 + 3];
        float4 An;
        An.x = Av.x * dpost + m0;  An.y = Av.y * dpost + m1;
        An.z = Av.z * dpost + m2;  An.w = Av.w * dpost + m3;
        *(float4*)&g_A[idx] = An;
        float4 Wv = *(const float4*)&g_wT[idx];
        float cs = c_t * Sv;
        Wv.x += etap * (a_t * Zf0 + b_t * m0) - etam * (cs + An.x);
        Wv.y += etap * (a_t * Zf1 + b_t * m1) - etam * (cs + An.y);
        Wv.z += etap * (a_t * Zf2 + b_t * m2) - etam * (cs + An.z);
        Wv.w += etap * (a_t * Zf3 + b_t * m3) - etam * (cs + An.w);
        Wv.x = fminf(fmaxf(Wv.x, -1.0f), 1.0f);
        Wv.y = fminf(fmaxf(Wv.y, -1.0f), 1.0f);
        Wv.z = fminf(fmaxf(Wv.z, -1.0f), 1.0f);
        Wv.w = fminf(fmaxf(Wv.w, -1.0f), 1.0f);
        *(float4*)&g_wT[idx] = Wv;
    }
}

// ---------------- K3: tiled transpose wT [I][O] -> output [O][I] -------------
__global__ __launch_bounds__(256) void k_wout(float* __restrict__ out) {
    __shared__ float tile[32][33];
    int tx = threadIdx.x, ty = threadIdx.y;           // block (32, 8)
    int x = blockIdx.x * 32 + tx;                     // o
    int y = blockIdx.y * 32 + ty;                     // i
#pragma unroll
    for (int j = 0; j < 32; j += 8)
        tile[ty + j][tx] = g_wT[(size_t)(y + j) * OSZ + x];
    __syncthreads();
    int xi = blockIdx.y * 32 + tx;
    int yo = blockIdx.x * 32 + ty;
#pragma unroll
    for (int j = 0; j < 32; j += 8)
        out[(size_t)(yo + j) * ISZ + xi] = tile[tx][ty + j];
}

// -----------------------------------------------------------------------------
extern "C" void kernel_launch(void* const* d_in, const int* in_sizes, int n_in,
                              void* d_out, int out_size) {
    const float* s    = (const float*)d_in[0];   // input_spikes [B,I]
    const float* w    = (const float*)d_in[1];   // weight [O,I]
    const float* bias = (const float*)d_in[2];   // bias [O]
    float* out  = (float*)d_out;
    float* zout = out;

    void *pA = nullptr, *pS = nullptr, *pV = nullptr, *pW = nullptr;
    cudaGetSymbolAddress(&pA, g_A);
    cudaGetSymbolAddress(&pS, g_S);
    cudaGetSymbolAddress(&pV, g_vf);
    cudaGetSymbolAddress(&pW, g_wT);

    float* v = (out_size >= 2 * BSZ * OSZ) ? (out + BSZ * OSZ) : (float*)pV;

    // per-launch state init (graph-replayed every run -> deterministic)
    cudaMemsetAsync(pA, 0, (size_t)ISZ * OSZ * sizeof(float));
    cudaMemsetAsync(pS, 0, (size_t)ISZ * sizeof(float));
    cudaMemsetAsync(v,  0, (size_t)BSZ * OSZ * sizeof(float));
    cudaMemsetAsync((char*)pW + (size_t)ISZ * OSZ * sizeof(float), 0,
                    OSZ * sizeof(float));        // zero pad row i=ISZ

    k_build_s<<<(NW * ISZ) / 256, 256>>>(s);
    k_build_csr<<<BSZ / 8, 256>>>(s);
    k_wT<<<dim3(ISZ / 32, OSZ / 32), dim3(32, 8)>>>(w);

    // fp32-iterated trace constants, matching the reference's iterative decay
    const float d = (float)exp(-0.05);   // decay_pre = decay_post = v_decay
    float p0 = 1.0f, p1 = 1.0f;
    for (int t = 0; t < SEQ; t++) {
        p0 = p0 * d;                 // tpre/tpost trajectory for s=0 (= d^t, fp32)
        p1 = p1 * d + 1.0f;          // tpre trajectory for s=1
        k_fwd<<<dim3(OSZ / 64, BSZ / 16), dim3(32, 16)>>>(bias, v, zout, d, t == SEQ - 1);
        k_upd<<<dim3(OSZ / 64, ISZ / 32), 128>>>(p0, p1 - p0, p0, d, 1e-3f, 1e-3f);
    }

    if (out_size >= 2 * BSZ * OSZ + ISZ * OSZ)
        k_wout<<<dim3(OSZ / 32, ISZ / 32), dim3(32, 8)>>>(out + 2 * BSZ * OSZ);
}

// round 16
// speedup vs baseline: 1.1240x; 1.0443x over previous
#include <cuda_runtime.h>
#include <math.h>

#define BSZ 1024
#define ISZ 2048
#define OSZ 1024
#define NW  32        // B/32 batch bit-words
#define SEQ 32
#define CSTRIDE 256   // CSR slots per batch (mean nnz ~102, +15 sigma < 256)

// ---------------- device state (all re-initialized every launch) -------------
__device__ float    g_wT[(ISZ+1)*OSZ]; // weight [I][O] (+ zero row at i=ISZ)
__device__ float    g_A [ISZ*OSZ];     // running A = sum d^{t-k} M_k, [I][O]
__device__ unsigned g_sb[NW*ISZ];      // input spike bits, [bg][i]
__device__ unsigned g_zb[NW*OSZ];      // output spike bits, [bg][o]
__device__ float    g_S [ISZ];         // per-input batch spike counts
__device__ float    g_vf[BSZ*OSZ];     // fallback v if out_size too small
__device__ unsigned short g_csr[BSZ*CSTRIDE];  // per-batch spiking-i lists
__device__ unsigned g_ns[BSZ];         // padded (x8) list length per batch

// ---------------- K0a: build input bitmasks + column counts ------------------
__global__ void k_build_s(const float* __restrict__ s) {
    int id = blockIdx.x * blockDim.x + threadIdx.x;
    if (id >= NW * ISZ) return;
    int i  = id & (ISZ - 1);
    int bg = id >> 11;
    unsigned w = 0u;
#pragma unroll
    for (int k = 0; k < 32; k++) {
        float x = s[(bg * 32 + k) * ISZ + i];
        w |= (x != 0.0f ? 1u : 0u) << k;
    }
    g_sb[bg * ISZ + i] = w;
    atomicAdd(&g_S[i], (float)__popc(w));   // exact integer adds: order-independent
}

// ---------------- K0c: build per-batch CSR spike lists (ballot scan) ---------
// One warp per batch; ascending i order; padded to a multiple of 8 with i=ISZ
// (a zero weight row), so the gather loop is branch-free.
__global__ __launch_bounds__(256) void k_build_csr(const float* __restrict__ s) {
    int b    = (blockIdx.x * 256 + threadIdx.x) >> 5;   // batch 0..1023
    int lane = threadIdx.x & 31;
    const float* row = s + (size_t)b * ISZ;
    unsigned short* out = g_csr + b * CSTRIDE;
    unsigned base = 0;
    for (int c = 0; c < ISZ / 32; c++) {
        float x = row[c * 32 + lane];
        unsigned m = __ballot_sync(0xFFFFFFFFu, x != 0.0f);
        if (m & (1u << lane)) {
            int pos = base + __popc(m & ((1u << lane) - 1u));
            out[pos] = (unsigned short)(c * 32 + lane);
        }
        base += __popc(m);
    }
    unsigned padded = (base + 7u) & ~7u;
    for (unsigned j = base + lane; j < padded; j += 32)
        out[j] = (unsigned short)ISZ;                   // zero-row pad
    if (lane == 0) g_ns[b] = padded;
}

// ---------------- K0b: tiled transpose weight [O][I] -> wT [I][O] ------------
__global__ __launch_bounds__(256) void k_wT(const float* __restrict__ w) {
    __shared__ float tile[32][33];
    int tx = threadIdx.x, ty = threadIdx.y;           // block (32, 8)
    int x = blockIdx.x * 32 + tx;                     // i
    int y = blockIdx.y * 32 + ty;                     // o
#pragma unroll
    for (int j = 0; j < 32; j += 8)
        tile[ty + j][tx] = w[(size_t)(y + j) * ISZ + x];
    __syncthreads();
    int xo = blockIdx.y * 32 + tx;
    int yi = blockIdx.x * 32 + ty;
#pragma unroll
    for (int j = 0; j < 32; j += 8)
        g_wT[(size_t)(yi + j) * OSZ + xo] = tile[tx][ty + j];
}

// ---------------- K1: CSR-gather forward + LIF + spike-bit build -------------
// grid (O/128, B/8), block (32, 8). Warp = one batch; lane owns 4 consecutive
// outputs (o..o+3): one LDG.128 per spike covers all four, so the index decode
// + IMAD.WIDE amortize over 4 contributions (~1.8 inst/contribution).
// 256-thread CTAs keep 4-5 CTAs/SM resident. Spike bits written as disjoint
// u8 quarters of g_zb (8 batches/CTA; no atomics, race-free). Accumulation:
// ascending k, 2 interleaved float4 partials -> deterministic per output.
__global__ __launch_bounds__(256) void k_fwd(const float* __restrict__ bias,
                                             float* __restrict__ v,
                                             float* __restrict__ zout,
                                             float vdecay, int last) {
    __shared__ unsigned short sidx[8 * CSTRIDE];      // 4KB
    __shared__ unsigned char  spk[8][128];            // 1KB pred matrix [b][o]
    int lane = threadIdx.x;
    int wy   = threadIdx.y;                           // batch-in-group 0..7
    int b    = blockIdx.y * 8 + wy;
    int o    = blockIdx.x * 128 + lane * 4;           // 4 consecutive outputs

    unsigned n = g_ns[b];
    {
        const unsigned short* src = g_csr + b * CSTRIDE;
        for (int k = lane; k < CSTRIDE; k += 32) sidx[wy * CSTRIDE + k] = src[k];
    }
    __syncwarp();                                     // per-warp private list

    const float4* wrow = (const float4*)(g_wT + o);   // stride OSZ/4 float4s
    float4 accA = make_float4(0.f, 0.f, 0.f, 0.f);
    float4 accB = make_float4(0.f, 0.f, 0.f, 0.f);
    const uint4* q4 = (const uint4*)(sidx + wy * CSTRIDE);
    unsigned n8 = n >> 3;
    for (unsigned k = 0; k < n8; k++) {
        uint4 q = q4[k];                              // 8 packed u16 indices
        float4 w0 = wrow[(q.x & 0xFFFFu) * (OSZ / 4)];
        float4 w1 = wrow[(q.x >> 16)     * (OSZ / 4)];
        float4 w2 = wrow[(q.y & 0xFFFFu) * (OSZ / 4)];
        float4 w3 = wrow[(q.y >> 16)     * (OSZ / 4)];
        float4 w4 = wrow[(q.z & 0xFFFFu) * (OSZ / 4)];
        float4 w5 = wrow[(q.z >> 16)     * (OSZ / 4)];
        float4 w6 = wrow[(q.w & 0xFFFFu) * (OSZ / 4)];
        float4 w7 = wrow[(q.w >> 16)     * (OSZ / 4)];
        accA.x += w0.x; accA.y += w0.y; accA.z += w0.z; accA.w += w0.w;
        accB.x += w1.x; accB.y += w1.y; accB.z += w1.z; accB.w += w1.w;
        accA.x += w2.x; accA.y += w2.y; accA.z += w2.z; accA.w += w2.w;
        accB.x += w3.x; accB.y += w3.y; accB.z += w3.z; accB.w += w3.w;
        accA.x += w4.x; accA.y += w4.y; accA.z += w4.z; accA.w += w4.w;
        accB.x += w5.x; accB.y += w5.y; accB.z += w5.z; accB.w += w5.w;
        accA.x += w6.x; accA.y += w6.y; accA.z += w6.z; accA.w += w6.w;
        accB.x += w7.x; accB.y += w7.y; accB.z += w7.z; accB.w += w7.w;
    }
    float4 sum;
    sum.x = accA.x + accB.x;  sum.y = accA.y + accB.y;  // fixed, deterministic
    sum.z = accA.z + accB.z;  sum.w = accA.w + accB.w;

    int idxv = b * OSZ + o;
    float4 v4  = *(float4*)&v[idxv];
    float4 bi4 = *(const float4*)&bias[o];
    float vv0 = v4.x * vdecay + sum.x + bi4.x;
    float vv1 = v4.y * vdecay + sum.y + bi4.y;
    float vv2 = v4.z * vdecay + sum.z + bi4.z;
    float vv3 = v4.w * vdecay + sum.w + bi4.w;
    bool s0 = (vv0 >= 1.0f), s1 = (vv1 >= 1.0f);
    bool s2 = (vv2 >= 1.0f), s3 = (vv3 >= 1.0f);
    if (last) {
        float4 z4 = make_float4(s0 ? 1.f : 0.f, s1 ? 1.f : 0.f,
                                s2 ? 1.f : 0.f, s3 ? 1.f : 0.f);
        *(float4*)&zout[idxv] = z4;
    }
    v4.x = s0 ? 0.0f : vv0;  v4.y = s1 ? 0.0f : vv1;   // v*(1-z) exactly
    v4.z = s2 ? 0.0f : vv2;  v4.w = s3 ? 0.0f : vv3;
    *(float4*)&v[idxv] = v4;
    spk[wy][lane * 4 + 0] = (unsigned char)s0;
    spk[wy][lane * 4 + 1] = (unsigned char)s1;
    spk[wy][lane * 4 + 2] = (unsigned char)s2;
    spk[wy][lane * 4 + 3] = (unsigned char)s3;
    __syncthreads();

    if (wy < 4) {                                     // bit-transpose 8x128
        int oc = wy * 32 + lane;
        unsigned char wd = 0;
#pragma unroll
        for (int k = 0; k < 8; k++)
            wd |= (unsigned char)(spk[k][oc] << k);
        int bg  = blockIdx.y >> 2;                    // 32-batch word index
        int qtr = blockIdx.y & 3;                     // byte within the word
        unsigned char* dst =
            (unsigned char*)&g_zb[bg * OSZ + blockIdx.x * 128 + oc];
        dst[qtr] = wd;                                // disjoint u8, race-free
    }
}

// ---------------- K2: M = z^T s popcount + A + w update, 4x4 register tile ---
// grid (O/64, I/32), block 128. Thread owns a 4o x 4il cell block.
__global__ __launch_bounds__(128) void k_upd(float a_t, float b_t, float c_t,
                                             float dpost, float etap, float etam) {
    __shared__ unsigned zt[NW * 64];   // [w][o-lane]   8KB
    __shared__ unsigned st[NW * 32];   // [w][il]       4KB
    __shared__ float    Ssh[32];
    int tid = threadIdx.x;
    int o0  = blockIdx.x * 64;
    int i0  = blockIdx.y * 32;

    for (int j = tid; j < NW * 64; j += 128) {
        int w = j >> 6, oo = j & 63;
        zt[j] = g_zb[w * OSZ + o0 + oo];
    }
    for (int j = tid; j < NW * 32; j += 128) {
        int w = j >> 5, il = j & 31;
        st[j] = g_sb[w * ISZ + i0 + il];
    }
    if (tid < 32) Ssh[tid] = g_S[i0 + tid];
    __syncthreads();

    int oq = (tid & 15) << 2;          // o-quad 0..60
    int iq = (tid >> 4) << 2;          // il-quad 0..28

    int cnt[16];
#pragma unroll
    for (int k = 0; k < 16; k++) cnt[k] = 0;
    int zc0 = 0, zc1 = 0, zc2 = 0, zc3 = 0;

#pragma unroll 8
    for (int w = 0; w < NW; w++) {
        uint4 z4 = *(const uint4*)&zt[w * 64 + oq];
        uint4 s4 = *(const uint4*)&st[w * 32 + iq];
        zc0 += __popc(z4.x); zc1 += __popc(z4.y);
        zc2 += __popc(z4.z); zc3 += __popc(z4.w);
        cnt[ 0] += __popc(s4.x & z4.x); cnt[ 1] += __popc(s4.x & z4.y);
        cnt[ 2] += __popc(s4.x & z4.z); cnt[ 3] += __popc(s4.x & z4.w);
        cnt[ 4] += __popc(s4.y & z4.x); cnt[ 5] += __popc(s4.y & z4.y);
        cnt[ 6] += __popc(s4.y & z4.z); cnt[ 7] += __popc(s4.y & z4.w);
        cnt[ 8] += __popc(s4.z & z4.x); cnt[ 9] += __popc(s4.z & z4.y);
        cnt[10] += __popc(s4.z & z4.z); cnt[11] += __popc(s4.z & z4.w);
        cnt[12] += __popc(s4.w & z4.x); cnt[13] += __popc(s4.w & z4.y);
        cnt[14] += __popc(s4.w & z4.z); cnt[15] += __popc(s4.w & z4.w);
    }
    float Zf0 = (float)zc0, Zf1 = (float)zc1, Zf2 = (float)zc2, Zf3 = (float)zc3;

#pragma unroll
    for (int c = 0; c < 4; c++) {
        int il  = iq + c;
        int idx = (i0 + il) * OSZ + o0 + oq;
        float Sv = Ssh[il];
        float4 Av = *(const float4*)&g_A[idx];
        float m0 = (float)cnt[c * 4 + 0], m1 = (float)cnt[c * 4 + 1];
        float m2 = (float)cnt[c * 4 + 2], m3 = (float)cnt[c * 4 + 3];
        float4 An;
        An.x = Av.x * dpost + m0;  An.y = Av.y * dpost + m1;
        An.z = Av.z * dpost + m2;  An.w = Av.w * dpost + m3;
        *(float4*)&g_A[idx] = An;
        float4 Wv = *(const float4*)&g_wT[idx];
        float cs = c_t * Sv;
        Wv.x += etap * (a_t * Zf0 + b_t * m0) - etam * (cs + An.x);
        Wv.y += etap * (a_t * Zf1 + b_t * m1) - etam * (cs + An.y);
        Wv.z += etap * (a_t * Zf2 + b_t * m2) - etam * (cs + An.z);
        Wv.w += etap * (a_t * Zf3 + b_t * m3) - etam * (cs + An.w);
        Wv.x = fminf(fmaxf(Wv.x, -1.0f), 1.0f);
        Wv.y = fminf(fmaxf(Wv.y, -1.0f), 1.0f);
        Wv.z = fminf(fmaxf(Wv.z, -1.0f), 1.0f);
        Wv.w = fminf(fmaxf(Wv.w, -1.0f), 1.0f);
        *(float4*)&g_wT[idx] = Wv;
    }
}

// ---------------- K3: tiled transpose wT [I][O] -> output [O][I] -------------
__global__ __launch_bounds__(256) void k_wout(float* __restrict__ out) {
    __shared__ float tile[32][33];
    int tx = threadIdx.x, ty = threadIdx.y;           // block (32, 8)
    int x = blockIdx.x * 32 + tx;                     // o
    int y = blockIdx.y * 32 + ty;                     // i
#pragma unroll
    for (int j = 0; j < 32; j += 8)
        tile[ty + j][tx] = g_wT[(size_t)(y + j) * OSZ + x];
    __syncthreads();
    int xi = blockIdx.y * 32 + tx;
    int yo = blockIdx.x * 32 + ty;
#pragma unroll
    for (int j = 0; j < 32; j += 8)
        out[(size_t)(yo + j) * ISZ + xi] = tile[tx][ty + j];
}

// -----------------------------------------------------------------------------
extern "C" void kernel_launch(void* const* d_in, const int* in_sizes, int n_in,
                              void* d_out, int out_size) {
    const float* s    = (const float*)d_in[0];   // input_spikes [B,I]
    const float* w    = (const float*)d_in[1];   // weight [O,I]
    const float* bias = (const float*)d_in[2];   // bias [O]
    float* out  = (float*)d_out;
    float* zout = out;

    void *pA = nullptr, *pS = nullptr, *pV = nullptr, *pW = nullptr;
    cudaGetSymbolAddress(&pA, g_A);
    cudaGetSymbolAddress(&pS, g_S);
    cudaGetSymbolAddress(&pV, g_vf);
    cudaGetSymbolAddress(&pW, g_wT);

    float* v = (out_size >= 2 * BSZ * OSZ) ? (out + BSZ * OSZ) : (float*)pV;

    // per-launch state init (graph-replayed every run -> deterministic)
    cudaMemsetAsync(pA, 0, (size_t)ISZ * OSZ * sizeof(float));
    cudaMemsetAsync(pS, 0, (size_t)ISZ * sizeof(float));
    cudaMemsetAsync(v,  0, (size_t)BSZ * OSZ * sizeof(float));
    cudaMemsetAsync((char*)pW + (size_t)ISZ * OSZ * sizeof(float), 0,
                    OSZ * sizeof(float));        // zero pad row i=ISZ

    k_build_s<<<(NW * ISZ) / 256, 256>>>(s);
    k_build_csr<<<BSZ / 8, 256>>>(s);
    k_wT<<<dim3(ISZ / 32, OSZ / 32), dim3(32, 8)>>>(w);

    // fp32-iterated trace constants, matching the reference's iterative decay
    const float d = (float)exp(-0.05);   // decay_pre = decay_post = v_decay
    float p0 = 1.0f, p1 = 1.0f;
    for (int t = 0; t < SEQ; t++) {
        p0 = p0 * d;                 // tpre/tpost trajectory for s=0 (= d^t, fp32)
        p1 = p1 * d + 1.0f;          // tpre trajectory for s=1
        k_fwd<<<dim3(OSZ / 128, BSZ / 8), dim3(32, 8)>>>(bias, v, zout, d, t == SEQ - 1);
        k_upd<<<dim3(OSZ / 64, ISZ / 32), 128>>>(p0, p1 - p0, p0, d, 1e-3f, 1e-3f);
    }

    if (out_size >= 2 * BSZ * OSZ + ISZ * OSZ)
        k_wout<<<dim3(OSZ / 32, ISZ / 32), dim3(32, 8)>>>(out + 2 * BSZ * OSZ);
}

// round 17
// speedup vs baseline: 1.1509x; 1.0239x over previous
#include <cuda_runtime.h>
#include <math.h>

#define BSZ 1024
#define ISZ 2048
#define OSZ 1024
#define NW  32        // B/32 batch bit-words
#define SEQ 32
#define CSTRIDE 256   // CSR slots per batch (mean nnz ~102, +15 sigma < 256)

// ---------------- device state -----------------------------------------------
__device__ float    g_wT[(ISZ+1)*OSZ]; // weight [I][O] (+ zero row at i=ISZ,
                                       //  never written -> stays 0 from init)
__device__ float    g_A [ISZ*OSZ];     // running A; re-seeded via dpost=0 at t=0
__device__ unsigned g_sb[NW*ISZ];      // input spike bits, [bg][i]
__device__ unsigned g_zb[NW*OSZ];      // output spike bits, [bg][o]
__device__ float    g_vf[BSZ*OSZ];     // fallback v if out_size too small
__device__ unsigned short g_csr[BSZ*CSTRIDE];  // per-batch spiking-i lists
__device__ unsigned g_ns[BSZ];         // padded (x8) list length per batch

// ---------------- K0a: build input bitmasks ----------------------------------
__global__ void k_build_s(const float* __restrict__ s) {
    int id = blockIdx.x * blockDim.x + threadIdx.x;
    if (id >= NW * ISZ) return;
    int i  = id & (ISZ - 1);
    int bg = id >> 11;
    unsigned w = 0u;
#pragma unroll
    for (int k = 0; k < 32; k++) {
        float x = s[(bg * 32 + k) * ISZ + i];
        w |= (x != 0.0f ? 1u : 0u) << k;
    }
    g_sb[bg * ISZ + i] = w;
}

// ---------------- K0c: build per-batch CSR spike lists (ballot scan) ---------
__global__ __launch_bounds__(256) void k_build_csr(const float* __restrict__ s) {
    int b    = (blockIdx.x * 256 + threadIdx.x) >> 5;   // batch 0..1023
    int lane = threadIdx.x & 31;
    const float* row = s + (size_t)b * ISZ;
    unsigned short* out = g_csr + b * CSTRIDE;
    unsigned base = 0;
    for (int c = 0; c < ISZ / 32; c++) {
        float x = row[c * 32 + lane];
        unsigned m = __ballot_sync(0xFFFFFFFFu, x != 0.0f);
        if (m & (1u << lane)) {
            int pos = base + __popc(m & ((1u << lane) - 1u));
            out[pos] = (unsigned short)(c * 32 + lane);
        }
        base += __popc(m);
    }
    unsigned padded = (base + 7u) & ~7u;
    for (unsigned j = base + lane; j < padded; j += 32)
        out[j] = (unsigned short)ISZ;                   // zero-row pad
    if (lane == 0) g_ns[b] = padded;
}

// ---------------- K0b: tiled transpose weight [O][I] -> wT [I][O] ------------
__global__ __launch_bounds__(256) void k_wT(const float* __restrict__ w) {
    __shared__ float tile[32][33];
    int tx = threadIdx.x, ty = threadIdx.y;           // block (32, 8)
    int x = blockIdx.x * 32 + tx;                     // i
    int y = blockIdx.y * 32 + ty;                     // o
#pragma unroll
    for (int j = 0; j < 32; j += 8)
        tile[ty + j][tx] = w[(size_t)(y + j) * ISZ + x];
    __syncthreads();
    int xo = blockIdx.y * 32 + tx;
    int yi = blockIdx.x * 32 + ty;
#pragma unroll
    for (int j = 0; j < 32; j += 8)
        g_wT[(size_t)(yi + j) * OSZ + xo] = tile[tx][ty + j];
}

// ---------------- K1: CSR-gather forward + LIF + spike-bit build -------------
// grid (O/128, B/8), block (32, 8). Warp = one batch; lane owns 4 consecutive
// outputs: one LDG.128 per spike covers all four. PDL: the static CSR prologue
// runs before cudaGridDependencySynchronize(), overlapping the predecessor.
// vdecay=0 at t=0 seeds v exactly (0*garbage + z_in; all values finite).
__global__ __launch_bounds__(256) void k_fwd(const float* __restrict__ bias,
                                             float* __restrict__ v,
                                             float* __restrict__ zout,
                                             float vdecay, int last) {
    __shared__ unsigned short sidx[8 * CSTRIDE];      // 4KB
    __shared__ unsigned char  spk[8][128];            // 1KB pred matrix [b][o]
    int lane = threadIdx.x;
    int wy   = threadIdx.y;                           // batch-in-group 0..7
    int b    = blockIdx.y * 8 + wy;
    int o    = blockIdx.x * 128 + lane * 4;           // 4 consecutive outputs

    unsigned n = g_ns[b];                             // static prologue
    {
        const unsigned short* src = g_csr + b * CSTRIDE;
        for (int k = lane; k < CSTRIDE; k += 32) sidx[wy * CSTRIDE + k] = src[k];
    }
    __syncwarp();                                     // per-warp private list

    cudaGridDependencySynchronize();                  // wait predecessor (wT, v)

    const float4* wrow = (const float4*)(g_wT + o);   // stride OSZ/4 float4s
    float4 accA = make_float4(0.f, 0.f, 0.f, 0.f);
    float4 accB = make_float4(0.f, 0.f, 0.f, 0.f);
    const uint4* q4 = (const uint4*)(sidx + wy * CSTRIDE);
    unsigned n8 = n >> 3;
    for (unsigned k = 0; k < n8; k++) {
        uint4 q = q4[k];                              // 8 packed u16 indices
        float4 w0 = wrow[(q.x & 0xFFFFu) * (OSZ / 4)];
        float4 w1 = wrow[(q.x >> 16)     * (OSZ / 4)];
        float4 w2 = wrow[(q.y & 0xFFFFu) * (OSZ / 4)];
        float4 w3 = wrow[(q.y >> 16)     * (OSZ / 4)];
        float4 w4 = wrow[(q.z & 0xFFFFu) * (OSZ / 4)];
        float4 w5 = wrow[(q.z >> 16)     * (OSZ / 4)];
        float4 w6 = wrow[(q.w & 0xFFFFu) * (OSZ / 4)];
        float4 w7 = wrow[(q.w >> 16)     * (OSZ / 4)];
        accA.x += w0.x; accA.y += w0.y; accA.z += w0.z; accA.w += w0.w;
        accB.x += w1.x; accB.y += w1.y; accB.z += w1.z; accB.w += w1.w;
        accA.x += w2.x; accA.y += w2.y; accA.z += w2.z; accA.w += w2.w;
        accB.x += w3.x; accB.y += w3.y; accB.z += w3.z; accB.w += w3.w;
        accA.x += w4.x; accA.y += w4.y; accA.z += w4.z; accA.w += w4.w;
        accB.x += w5.x; accB.y += w5.y; accB.z += w5.z; accB.w += w5.w;
        accA.x += w6.x; accA.y += w6.y; accA.z += w6.z; accA.w += w6.w;
        accB.x += w7.x; accB.y += w7.y; accB.z += w7.z; accB.w += w7.w;
    }
    float4 sum;
    sum.x = accA.x + accB.x;  sum.y = accA.y + accB.y;  // fixed, deterministic
    sum.z = accA.z + accB.z;  sum.w = accA.w + accB.w;

    int idxv = b * OSZ + o;
    float4 v4  = *(float4*)&v[idxv];
    float4 bi4 = *(const float4*)&bias[o];
    float vv0 = v4.x * vdecay + sum.x + bi4.x;
    float vv1 = v4.y * vdecay + sum.y + bi4.y;
    float vv2 = v4.z * vdecay + sum.z + bi4.z;
    float vv3 = v4.w * vdecay + sum.w + bi4.w;
    bool s0 = (vv0 >= 1.0f), s1 = (vv1 >= 1.0f);
    bool s2 = (vv2 >= 1.0f), s3 = (vv3 >= 1.0f);
    if (last) {
        float4 z4 = make_float4(s0 ? 1.f : 0.f, s1 ? 1.f : 0.f,
                                s2 ? 1.f : 0.f, s3 ? 1.f : 0.f);
        *(float4*)&zout[idxv] = z4;
    }
    v4.x = s0 ? 0.0f : vv0;  v4.y = s1 ? 0.0f : vv1;   // v*(1-z) exactly
    v4.z = s2 ? 0.0f : vv2;  v4.w = s3 ? 0.0f : vv3;
    *(float4*)&v[idxv] = v4;
    spk[wy][lane * 4 + 0] = (unsigned char)s0;
    spk[wy][lane * 4 + 1] = (unsigned char)s1;
    spk[wy][lane * 4 + 2] = (unsigned char)s2;
    spk[wy][lane * 4 + 3] = (unsigned char)s3;
    __syncthreads();

    if (wy < 4) {                                     // bit-transpose 8x128
        int oc = wy * 32 + lane;
        unsigned char wd = 0;
#pragma unroll
        for (int k = 0; k < 8; k++)
            wd |= (unsigned char)(spk[k][oc] << k);
        int bg  = blockIdx.y >> 2;                    // 32-batch word index
        int qtr = blockIdx.y & 3;                     // byte within the word
        unsigned char* dst =
            (unsigned char*)&g_zb[bg * OSZ + blockIdx.x * 128 + oc];
        dst[qtr] = wd;                                // disjoint u8, race-free
    }
}

// ---------------- K2: M = z^T s popcount + A + w update, 4x4 register tile ---
// grid (O/64, I/32), block 128. Thread owns a 4o x 4il cell block.
// S (per-input spike counts) computed in-kernel from the st tile (exact ints,
// identical to the old precomputed g_S). dpost=0 at t=0 seeds A exactly.
// PDL: static st tile + Ssh before griddepsync; dependent zt after.
__global__ __launch_bounds__(128) void k_upd(float a_t, float b_t, float c_t,
                                             float dpost, float etap, float etam) {
    __shared__ unsigned zt[NW * 64];   // [w][o-lane]   8KB
    __shared__ unsigned st[NW * 32];   // [w][il]       4KB
    __shared__ float    Ssh[32];
    int tid = threadIdx.x;
    int o0  = blockIdx.x * 64;
    int i0  = blockIdx.y * 32;

    for (int j = tid; j < NW * 32; j += 128) {        // static prologue
        int w = j >> 5, il = j & 31;
        st[j] = g_sb[w * ISZ + i0 + il];
    }
    __syncthreads();
    if (tid < 32) {                                   // S[i] = sum_w popc
        int sc = 0;
#pragma unroll
        for (int w = 0; w < NW; w++) sc += __popc(st[w * 32 + tid]);
        Ssh[tid] = (float)sc;
    }

    cudaGridDependencySynchronize();                  // wait k_fwd (g_zb)

    for (int j = tid; j < NW * 64; j += 128) {
        int w = j >> 6, oo = j & 63;
        zt[j] = g_zb[w * OSZ + o0 + oo];
    }
    __syncthreads();

    int oq = (tid & 15) << 2;          // o-quad 0..60
    int iq = (tid >> 4) << 2;          // il-quad 0..28

    int cnt[16];
#pragma unroll
    for (int k = 0; k < 16; k++) cnt[k] = 0;
    int zc0 = 0, zc1 = 0, zc2 = 0, zc3 = 0;

#pragma unroll 8
    for (int w = 0; w < NW; w++) {
        uint4 z4 = *(const uint4*)&zt[w * 64 + oq];
        uint4 s4 = *(const uint4*)&st[w * 32 + iq];
        zc0 += __popc(z4.x); zc1 += __popc(z4.y);
        zc2 += __popc(z4.z); zc3 += __popc(z4.w);
        cnt[ 0] += __popc(s4.x & z4.x); cnt[ 1] += __popc(s4.x & z4.y);
        cnt[ 2] += __popc(s4.x & z4.z); cnt[ 3] += __popc(s4.x & z4.w);
        cnt[ 4] += __popc(s4.y & z4.x); cnt[ 5] += __popc(s4.y & z4.y);
        cnt[ 6] += __popc(s4.y & z4.z); cnt[ 7] += __popc(s4.y & z4.w);
        cnt[ 8] += __popc(s4.z & z4.x); cnt[ 9] += __popc(s4.z & z4.y);
        cnt[10] += __popc(s4.z & z4.z); cnt[11] += __popc(s4.z & z4.w);
        cnt[12] += __popc(s4.w & z4.x); cnt[13] += __popc(s4.w & z4.y);
        cnt[14] += __popc(s4.w & z4.z); cnt[15] += __popc(s4.w & z4.w);
    }
    float Zf0 = (float)zc0, Zf1 = (float)zc1, Zf2 = (float)zc2, Zf3 = (float)zc3;

#pragma unroll
    for (int c = 0; c < 4; c++) {
        int il  = iq + c;
        int idx = (i0 + il) * OSZ + o0 + oq;
        float Sv = Ssh[il];
        float4 Av = *(const float4*)&g_A[idx];
        float m0 = (float)cnt[c * 4 + 0], m1 = (float)cnt[c * 4 + 1];
        float m2 = (float)cnt[c * 4 + 2], m3 = (float)cnt[c * 4 + 3];
        float4 An;
        An.x = Av.x * dpost + m0;  An.y = Av.y * dpost + m1;
        An.z = Av.z * dpost + m2;  An.w = Av.w * dpost + m3;
        *(float4*)&g_A[idx] = An;
        float4 Wv = *(const float4*)&g_wT[idx];
        float cs = c_t * Sv;
        Wv.x += etap * (a_t * Zf0 + b_t * m0) - etam * (cs + An.x);
        Wv.y += etap * (a_t * Zf1 + b_t * m1) - etam * (cs + An.y);
        Wv.z += etap * (a_t * Zf2 + b_t * m2) - etam * (cs + An.z);
        Wv.w += etap * (a_t * Zf3 + b_t * m3) - etam * (cs + An.w);
        Wv.x = fminf(fmaxf(Wv.x, -1.0f), 1.0f);
        Wv.y = fminf(fmaxf(Wv.y, -1.0f), 1.0f);
        Wv.z = fminf(fmaxf(Wv.z, -1.0f), 1.0f);
        Wv.w = fminf(fmaxf(Wv.w, -1.0f), 1.0f);
        *(float4*)&g_wT[idx] = Wv;
    }
}

// ---------------- K3: tiled transpose wT [I][O] -> output [O][I] -------------
__global__ __launch_bounds__(256) void k_wout(float* __restrict__ out) {
    __shared__ float tile[32][33];
    int tx = threadIdx.x, ty = threadIdx.y;           // block (32, 8)
    int x = blockIdx.x * 32 + tx;                     // o
    int y = blockIdx.y * 32 + ty;                     // i
    cudaGridDependencySynchronize();
#pragma unroll
    for (int j = 0; j < 32; j += 8)
        tile[ty + j][tx] = g_wT[(size_t)(y + j) * OSZ + x];
    __syncthreads();
    int xi = blockIdx.y * 32 + tx;
    int yo = blockIdx.x * 32 + ty;
#pragma unroll
    for (int j = 0; j < 32; j += 8)
        out[(size_t)(yo + j) * ISZ + xi] = tile[tx][ty + j];
}

// ---------------- host: PDL launch helper ------------------------------------
template <typename F, typename... Args>
static inline void launch_pdl(F* f, dim3 g, dim3 b, Args... args) {
    cudaLaunchConfig_t cfg = {};
    cfg.gridDim = g;
    cfg.blockDim = b;
    cfg.dynamicSmemBytes = 0;
    cfg.stream = 0;
    cudaLaunchAttribute at;
    at.id = cudaLaunchAttributeProgrammaticStreamSerialization;
    at.val.programmaticStreamSerializationAllowed = 1;
    cfg.attrs = &at;
    cfg.numAttrs = 1;
    cudaLaunchKernelEx(&cfg, f, args...);
}

// -----------------------------------------------------------------------------
extern "C" void kernel_launch(void* const* d_in, const int* in_sizes, int n_in,
                              void* d_out, int out_size) {
    const float* s    = (const float*)d_in[0];   // input_spikes [B,I]
    const float* w    = (const float*)d_in[1];   // weight [O,I]
    const float* bias = (const float*)d_in[2];   // bias [O]
    float* out  = (float*)d_out;
    float* zout = out;

    void* pV = nullptr;
    cudaGetSymbolAddress(&pV, g_vf);
    float* v = (out_size >= 2 * BSZ * OSZ) ? (out + BSZ * OSZ) : (float*)pV;

    k_build_s<<<(NW * ISZ) / 256, 256>>>(s);
    k_build_csr<<<BSZ / 8, 256>>>(s);
    k_wT<<<dim3(ISZ / 32, OSZ / 32), dim3(32, 8)>>>(w);

    // fp32-iterated trace constants, matching the reference's iterative decay
    const float d = (float)exp(-0.05);   // decay_pre = decay_post = v_decay
    float p0 = 1.0f, p1 = 1.0f;
    for (int t = 0; t < SEQ; t++) {
        p0 = p0 * d;                 // tpre/tpost trajectory for s=0 (= d^t, fp32)
        p1 = p1 * d + 1.0f;          // tpre trajectory for s=1
        float vdec  = (t == 0) ? 0.0f : d;   // t=0: exact seed, no memset needed
        float dpost = (t == 0) ? 0.0f : d;
        if (t == 0)
            k_fwd<<<dim3(OSZ / 128, BSZ / 8), dim3(32, 8)>>>(
                bias, v, zout, vdec, (int)(t == SEQ - 1));
        else
            launch_pdl(k_fwd, dim3(OSZ / 128, BSZ / 8), dim3(32, 8),
                       bias, v, zout, vdec, (int)(t == SEQ - 1));
        launch_pdl(k_upd, dim3(OSZ / 64, ISZ / 32), dim3(128, 1, 1),
                   p0, p1 - p0, p0, dpost, 1e-3f, 1e-3f);
    }

    if (out_size >= 2 * BSZ * OSZ + ISZ * OSZ)
        launch_pdl(k_wout, dim3(OSZ / 32, ISZ / 32), dim3(32, 8),
                   out + 2 * BSZ * OSZ);
}